// round 6
// baseline (speedup 1.0000x reference)
#include <cuda_runtime.h>

#define N_NODES   8192
#define T_TYPES   4
#define E_EDGES   131072        // = 2^17
#define H_HEADS   4
#define D_DIM     32
#define NEG_SLOPE 0.2f

#define BMP_WORDS (1u << 21)    // 2^26 keys / 32 = 8 MiB exact bitmap
#define DUP_BITS  16
#define DUP_SIZE  (1u << DUP_BITS)
#define DUP_MASK  (DUP_SIZE - 1u)

#define PREP_BLOCKS 32                                   // 8192/256
#define BLD_EDGE_BLOCKS ((T_TYPES * E_EDGES) / (256 * 4))  // 512
#define K2_BLOCKS       ((T_TYPES * E_EDGES) / (256 * 2))  // 1024

// Scratch — zero-init at module load; K3 re-clears what K1/K2 dirtied.
__device__ unsigned int g_bmp[BMP_WORDS];
__device__ unsigned int g_dkey[DUP_SIZE];          // 0=empty else key+1
__device__ unsigned int g_dmul[DUP_SIZE];          // extra arrivals (m-1)
__device__ unsigned long long g_dagg[DUP_SIZE];    // lo32: packed counts, hi32: arrivals
__device__ float4 g_acc[N_NODES * 2];              // [d0,n0,d1,n1][d2,n2,d3,n3]
__device__ float4 g_srcP[N_NODES * 2];             // exp(si*wsrc_h), exp(.2*si*wsrc_h)
__device__ float4 g_tgtP[N_NODES * 2];
__device__ float4 g_Gt [T_TYPES];
__device__ float4 g_G5t[T_TYPES];
__device__ float g_wsrc[H_HEADS];
__device__ float g_wtgt[H_HEADS];
__device__ float g_embterm[H_HEADS * T_TYPES];
__device__ float g_stotal;

__device__ __forceinline__ unsigned int hashk(unsigned int key) {
    unsigned int h = key * 2654435761u;
    return h ^ (h >> 15);
}

// ---------------------------------------------------------------------------
// K1: blocks [0,32) exp tables + params; blocks [32,544): dup detect, 4 edges
// per thread with batched independent atomicOrs (MLP=4).
// ---------------------------------------------------------------------------
__global__ void __launch_bounds__(256) k_build(
        const float* __restrict__ scores,
        const float* __restrict__ emb,
        const float* __restrict__ W,
        const int*   __restrict__ ei) {
    if (blockIdx.x < PREP_BLOCKS) {
        int i = blockIdx.x * 256 + threadIdx.x;
        float s = scores[i];
        float E[4], E5[4], F[4], F5[4];
        #pragma unroll
        for (int h = 0; h < H_HEADS; h++) {
            float ws = __ldg(W + h * (D_DIM + 2));
            float wt = __ldg(W + h * (D_DIM + 2) + D_DIM + 1);
            E [h] = __expf(s * ws);
            E5[h] = __expf(NEG_SLOPE * s * ws);
            F [h] = __expf(s * wt);
            F5[h] = __expf(NEG_SLOPE * s * wt);
        }
        g_srcP[2 * i    ] = make_float4(E [0], E [1], E [2], E [3]);
        g_srcP[2 * i + 1] = make_float4(E5[0], E5[1], E5[2], E5[3]);
        g_tgtP[2 * i    ] = make_float4(F [0], F [1], F [2], F [3]);
        g_tgtP[2 * i + 1] = make_float4(F5[0], F5[1], F5[2], F5[3]);

        if (blockIdx.x == 0) {
            __shared__ float red[256];
            int tid = threadIdx.x;
            float ss = 0.f;
            for (int k = tid; k < N_NODES; k += 256) ss += scores[k];
            red[tid] = ss;
            __syncthreads();
            for (int o = 128; o > 0; o >>= 1) {
                if (tid < o) red[tid] += red[tid + o];
                __syncthreads();
            }
            if (tid == 0) g_stotal = red[0];

            if (tid < H_HEADS * T_TYPES) {
                int t = tid >> 2, h = tid & 3;
                float acc = 0.f;
                #pragma unroll
                for (int d = 0; d < D_DIM; d++)
                    acc += emb[t * D_DIM + d] * W[h * (D_DIM + 2) + 1 + d];
                g_embterm[h * T_TYPES + t] = acc;
                ((float*)g_Gt )[t * 4 + h] = __expf(acc);
                ((float*)g_G5t)[t * 4 + h] = __expf(NEG_SLOPE * acc);
            }
            if (tid >= 64 && tid < 64 + H_HEADS) {
                int h = tid - 64;
                g_wsrc[h] = W[h * (D_DIM + 2)];
                g_wtgt[h] = W[h * (D_DIM + 2) + D_DIM + 1];
            }
        }
    } else {
        int id   = (blockIdx.x - PREP_BLOCKS) * 256 + threadIdx.x;
        int base = id * 4;                      // 4 consecutive edges, same t
        int t = base >> 17;
        int e = base & (E_EDGES - 1);
        int4 s4 = __ldg((const int4*)(ei + (t * 2    ) * E_EDGES + e));
        int4 t4 = __ldg((const int4*)(ei + (t * 2 + 1) * E_EDGES + e));

        unsigned int key[4];
        key[0] = ((unsigned)s4.x << 13) | (unsigned)t4.x;
        key[1] = ((unsigned)s4.y << 13) | (unsigned)t4.y;
        key[2] = ((unsigned)s4.z << 13) | (unsigned)t4.z;
        key[3] = ((unsigned)s4.w << 13) | (unsigned)t4.w;

        unsigned int old[4];
        #pragma unroll
        for (int k = 0; k < 4; k++)
            old[k] = atomicOr(&g_bmp[key[k] >> 5], 1u << (key[k] & 31u));

        #pragma unroll
        for (int k = 0; k < 4; k++) {
            if (old[k] & (1u << (key[k] & 31u))) {
                unsigned int hh = hashk(key[k]) & DUP_MASK;
                while (true) {
                    unsigned int o = atomicCAS(&g_dkey[hh], 0u, key[k] + 1u);
                    if (o == 0u || o == key[k] + 1u) break;
                    hh = (hh + 1u) & DUP_MASK;
                }
                atomicAdd(&g_dmul[hh], 1u);
            }
        }
    }
}

// ---------------------------------------------------------------------------
// K2: 2 edges/thread. Singleton fast path (no MUFU); dup groups via packed
// u64 atomic, last arriver emits the group term with __expf.
// ---------------------------------------------------------------------------
__device__ __forceinline__ void process_edge(
        const float* __restrict__ scores,
        unsigned int src, unsigned int tgt, int t,
        float4 G, float4 G5) {
    unsigned int key = (src << 13) | tgt;

    // probe tiny dup hash (complete & read-only after K1)
    unsigned int hh = hashk(key) & DUP_MASK;
    int dslot = -1;
    while (true) {
        unsigned int k2 = g_dkey[hh];
        if (k2 == 0u) break;
        if (k2 == key + 1u) { dslot = (int)hh; break; }
        hh = (hh + 1u) & DUP_MASK;
    }

    float sj = __ldg(scores + tgt);
    float ex0, ex1, ex2, ex3;

    if (dslot < 0) {
        float4 E  = g_srcP[2 * src], E5 = g_srcP[2 * src + 1];
        float4 F  = g_tgtP[2 * tgt], F5 = g_tgtP[2 * tgt + 1];
        float p, q;
        p = E.x * F.x * G.x;  q = E5.x * F5.x * G5.x;  ex0 = (p >= 1.f ? p : q) - 1.f;
        p = E.y * F.y * G.y;  q = E5.y * F5.y * G5.y;  ex1 = (p >= 1.f ? p : q) - 1.f;
        p = E.z * F.z * G.z;  q = E5.z * F5.z * G5.z;  ex2 = (p >= 1.f ? p : q) - 1.f;
        p = E.w * F.w * G.w;  q = E5.w * F5.w * G5.w;  ex3 = (p >= 1.f ? p : q) - 1.f;
    } else {
        unsigned long long inc = (1ULL << 32) | (unsigned long long)(1u << (t * 8));
        unsigned long long old = atomicAdd(&g_dagg[dslot], inc);
        unsigned int arrived = (unsigned int)(old >> 32);
        unsigned int m = g_dmul[dslot] + 1u;          // total multiplicity
        if (arrived != m - 1u) return;                // not the last arriver
        unsigned int c = (unsigned int)(old & 0xFFFFFFFFull) + (1u << (t * 8));
        float si = __ldg(scores + src);
        float c0 = (float)( c        & 0xFFu);
        float c1 = (float)((c >> 8 ) & 0xFFu);
        float c2 = (float)((c >> 16) & 0xFFu);
        float c3 = (float)((c >> 24) & 0xFFu);
        float ctot = c0 + c1 + c2 + c3;
        float exh[4];
        #pragma unroll
        for (int h = 0; h < H_HEADS; h++) {
            float a = (si * g_wsrc[h] + sj * g_wtgt[h]) * ctot
                    + c0 * g_embterm[h * T_TYPES + 0]
                    + c1 * g_embterm[h * T_TYPES + 1]
                    + c2 * g_embterm[h * T_TYPES + 2]
                    + c3 * g_embterm[h * T_TYPES + 3];
            a = (a >= 0.f) ? a : NEG_SLOPE * a;
            exh[h] = __expf(a) - 1.f;
        }
        ex0 = exh[0]; ex1 = exh[1]; ex2 = exh[2]; ex3 = exh[3];
    }

    float4* dst = &g_acc[src * 2];
    asm volatile("red.global.add.v4.f32 [%0], {%1,%2,%3,%4};"
                 :: "l"(dst), "f"(ex0), "f"(ex0 * sj),
                    "f"(ex1), "f"(ex1 * sj) : "memory");
    asm volatile("red.global.add.v4.f32 [%0], {%1,%2,%3,%4};"
                 :: "l"(dst + 1), "f"(ex2), "f"(ex2 * sj),
                    "f"(ex3), "f"(ex3 * sj) : "memory");
}

__global__ void __launch_bounds__(256) k_edges(
        const float* __restrict__ scores,
        const int*   __restrict__ ei) {
    int id   = blockIdx.x * 256 + threadIdx.x;
    int base = id * 2;                          // 2 consecutive edges, same t
    int t = base >> 17;
    int e = base & (E_EDGES - 1);
    int2 s2 = __ldg((const int2*)(ei + (t * 2    ) * E_EDGES + e));
    int2 t2 = __ldg((const int2*)(ei + (t * 2 + 1) * E_EDGES + e));

    float4 G = g_Gt[t], G5 = g_G5t[t];
    process_edge(scores, (unsigned)s2.x, (unsigned)t2.x, t, G, G5);
    process_edge(scores, (unsigned)s2.y, (unsigned)t2.y, t, G, G5);
}

// ---------------------------------------------------------------------------
// K3: blocks [0,32) finalize + reset g_acc; rest clear bitmap + dup hash.
// ---------------------------------------------------------------------------
__global__ void k_final(float* __restrict__ out) {
    if (blockIdx.x < PREP_BLOCKS) {
        int i = blockIdx.x * 256 + threadIdx.x;
        float st = g_stotal;
        float4 a0 = g_acc[i * 2];
        float4 a1 = g_acc[i * 2 + 1];
        float acc = (st + a0.y) / ((float)N_NODES + a0.x)
                  + (st + a0.w) / ((float)N_NODES + a0.z)
                  + (st + a1.y) / ((float)N_NODES + a1.x)
                  + (st + a1.w) / ((float)N_NODES + a1.z);
        out[i] = acc * (1.f / (float)H_HEADS);
        g_acc[i * 2]     = make_float4(0.f, 0.f, 0.f, 0.f);
        g_acc[i * 2 + 1] = make_float4(0.f, 0.f, 0.f, 0.f);
    } else {
        unsigned int tidc   = (blockIdx.x - PREP_BLOCKS) * 256 + threadIdx.x;
        unsigned int stride = (gridDim.x - PREP_BLOCKS) * 256;
        uint4 z4 = make_uint4(0u, 0u, 0u, 0u);
        uint4* bmp4 = (uint4*)g_bmp;
        for (unsigned int k = tidc; k < (BMP_WORDS >> 2); k += stride) bmp4[k] = z4;
        for (unsigned int k = tidc; k < DUP_SIZE; k += stride) {
            g_dkey[k] = 0u;
            g_dmul[k] = 0u;
            g_dagg[k] = 0ull;
        }
    }
}

// ---------------------------------------------------------------------------
extern "C" void kernel_launch(void* const* d_in, const int* in_sizes, int n_in,
                              void* d_out, int out_size) {
    const float* scores = (const float*)d_in[0];   // (N, 1)
    const float* emb    = (const float*)d_in[1];   // (T, D)
    const int*   ei     = (const int*)  d_in[2];   // (T, 2, E)
    const float* W      = (const float*)d_in[3];   // (H, D+2, 1)
    float*       out    = (float*)d_out;           // (N, 1)

    k_build<<<PREP_BLOCKS + BLD_EDGE_BLOCKS, 256>>>(scores, emb, W, ei);
    k_edges<<<K2_BLOCKS, 256>>>(scores, ei);
    k_final<<<PREP_BLOCKS + 2016, 256>>>(out);
}